// round 8
// baseline (speedup 1.0000x reference)
#include <cuda_runtime.h>
#include <cstdint>
#include <cstddef>

// Problem constants
#define B_   4
#define C_   192
#define H_   128
#define W_   128
#define P_   16384
#define ND   3
#define C2   64
#define NH   2
#define HD   32
#define MQKV 576
#define SCALE 0.17677669529663687f   // 32^-0.5

// Scratch (alloc-free: __device__ globals)
__device__ float g_x  [(size_t)B_*C_*P_];
__device__ float g_qkv[(size_t)B_*MQKV*P_];
__device__ float g_xo [(size_t)B_*C_*P_];

// ---------------------------------------------------------------------------
// Stage 1: depthwise 3x3 conv (zero pad) + residual + bias
// ---------------------------------------------------------------------------
__global__ __launch_bounds__(256) void pos_kernel(
    const float* __restrict__ x, const float* __restrict__ pw,
    const float* __restrict__ pb)
{
    int idx = blockIdx.x * 256 + threadIdx.x;
    if (idx >= B_*C_*P_) return;
    int pix = idx & (P_-1);
    int bc  = idx >> 14;
    int c   = bc % C_;
    int y  = pix >> 7;
    int xx = pix & 127;
    const float* xb = x + (size_t)bc * P_;
    const float* w  = pw + c * 9;
    float s = x[idx];
    #pragma unroll
    for (int kh = 0; kh < 3; kh++) {
        int yy = y + kh - 1;
        if (yy < 0 || yy >= H_) continue;
        #pragma unroll
        for (int kw = 0; kw < 3; kw++) {
            int xc = xx + kw - 1;
            if (xc < 0 || xc >= W_) continue;
            s += xb[yy * W_ + xc] * w[kh * 3 + kw];
        }
    }
    g_x[idx] = s + pb[c];
}

// ---------------------------------------------------------------------------
// tf32 mma.sync GEMM:  Y[b, m, p] = sum_c Wm[m, c] * X[b, c, p]
// Block = one 128-pixel tile for one batch; full-K X tile (192x128) resident
// in SMEM across the internal m-loop (96 out-channels per step).
// 384 threads = 12 warps (3m x 4n), warp tile 32x32 via m16n8k8 tf32 HMMA.
// A stored with (k, k+4) pair-permute so fragment loads are LDS.64.
// ---------------------------------------------------------------------------
#define GBM 96
#define GBN 128
#define GK  192
#define NKS 24             // k-steps of 8
#define KP2 200            // A row stride (floats); pos = r*200 + s*8 + 2*lc (+1)
#define BNP 136            // B row pad: lc groups hit disjoint 8-bank ranges
#define OP  132            // epilogue stage row pad
#define SM_AS_OFF (GK * BNP)                  // Bs: 26112 floats
#define SM_FLOATS (SM_AS_OFF + GBM * KP2)     // + As 19200 floats = 45312
#define SM_BYTES  (SM_FLOATS * 4)             // 181248 bytes

__device__ __forceinline__ float f2tf(float f) {
    uint32_t u;
    asm("cvt.rna.tf32.f32 %0, %1;" : "=r"(u) : "f"(f));
    return __uint_as_float(u);
}

__device__ __forceinline__ void mma_tf32(float (&d)[4], const uint32_t (&a)[4],
                                         const uint32_t (&b)[2]) {
    asm volatile(
        "mma.sync.aligned.m16n8k8.row.col.f32.tf32.tf32.f32 "
        "{%0,%1,%2,%3}, {%4,%5,%6,%7}, {%8,%9}, {%0,%1,%2,%3};"
        : "+f"(d[0]), "+f"(d[1]), "+f"(d[2]), "+f"(d[3])
        : "r"(a[0]), "r"(a[1]), "r"(a[2]), "r"(a[3]), "r"(b[0]), "r"(b[1]));
}

__global__ __launch_bounds__(384, 1) void gemm_mma(
    const float* __restrict__ Wm, const float* __restrict__ X,
    float* __restrict__ Y, int Mtot)
{
    extern __shared__ float sm[];
    float* Bs = sm;                 // [GK][BNP], k-major
    float* As = sm + SM_AS_OFF;     // [GBM][KP2] pair-permuted; reused as epi stage
    const uint32_t* Bsu = reinterpret_cast<const uint32_t*>(Bs);

    int tid  = threadIdx.x;
    int lane = tid & 31;
    int wid  = tid >> 5;
    int wm   = wid % 3;             // 3 warps along m
    int wn   = wid / 3;             // 4 warps along n
    int b    = blockIdx.y;
    int n0   = blockIdx.x * GBN;
    const float* Xb = X + (size_t)b * C_ * P_;
    float* Yb = Y + (size_t)b * Mtot * P_;

    // Fill Bs once: X[k][n0..n0+127] as tf32 bits. 6144 float4s / 384 = 16 each.
    #pragma unroll
    for (int i = 0; i < 16; i++) {
        int idx = tid + i * 384;
        int row = idx >> 5;
        int c4  = (idx & 31) << 2;
        float4 v = *reinterpret_cast<const float4*>(Xb + (size_t)row * P_ + n0 + c4);
        float4 t;
        t.x = f2tf(v.x); t.y = f2tf(v.y); t.z = f2tf(v.z); t.w = f2tf(v.w);
        *reinterpret_cast<float4*>(Bs + row * BNP + c4) = t;
    }

    int lr = lane >> 2;   // 0..7
    int lc = lane & 3;    // 0..3

    for (int m0 = 0; m0 < Mtot; m0 += GBM) {
        __syncthreads();   // Bs ready (iter 0); prior epilogue consumed (iter >0)

        // Fill As pair-permuted: 96 rows x 24 ksteps; thread handles one
        // (row, s) chunk of 8 floats -> 4 STS.64 of (k, k+4) pairs.
        #pragma unroll
        for (int i = 0; i < 6; i++) {
            int idx = tid + i * 384;          // 2304 chunks
            int row = idx / NKS;
            int s   = idx - row * NKS;
            const float* wp = Wm + (size_t)(m0 + row) * GK + s * 8;
            float4 v0 = *reinterpret_cast<const float4*>(wp);
            float4 v1 = *reinterpret_cast<const float4*>(wp + 4);
            float* dst = As + row * KP2 + s * 8;
            float2 p;
            p.x = f2tf(v0.x); p.y = f2tf(v1.x);
            *reinterpret_cast<float2*>(dst)     = p;
            p.x = f2tf(v0.y); p.y = f2tf(v1.y);
            *reinterpret_cast<float2*>(dst + 2) = p;
            p.x = f2tf(v0.z); p.y = f2tf(v1.z);
            *reinterpret_cast<float2*>(dst + 4) = p;
            p.x = f2tf(v0.w); p.y = f2tf(v1.w);
            *reinterpret_cast<float2*>(dst + 6) = p;
        }
        __syncthreads();

        float acc[2][4][4];
        #pragma unroll
        for (int mt = 0; mt < 2; mt++)
            #pragma unroll
            for (int nt = 0; nt < 4; nt++)
                #pragma unroll
                for (int r = 0; r < 4; r++) acc[mt][nt][r] = 0.f;

        #pragma unroll
        for (int s = 0; s < NKS; s++) {
            int k = s * 8;
            uint32_t a[2][4], bf[4][2];
            #pragma unroll
            for (int mt = 0; mt < 2; mt++) {
                int r = wm * 32 + mt * 16 + lr;
                uint2 u0 = *reinterpret_cast<const uint2*>(As + r * KP2 + k + 2 * lc);
                uint2 u1 = *reinterpret_cast<const uint2*>(As + (r + 8) * KP2 + k + 2 * lc);
                a[mt][0] = u0.x; a[mt][2] = u0.y;   // (row r,   k+lc), (row r,   k+lc+4)
                a[mt][1] = u1.x; a[mt][3] = u1.y;   // (row r+8, ...)
            }
            #pragma unroll
            for (int nt = 0; nt < 4; nt++) {
                int c0 = (k + lc) * BNP + wn * 32 + nt * 8 + lr;
                bf[nt][0] = Bsu[c0];
                bf[nt][1] = Bsu[c0 + 4 * BNP];
            }
            #pragma unroll
            for (int mt = 0; mt < 2; mt++)
                #pragma unroll
                for (int nt = 0; nt < 4; nt++)
                    mma_tf32(acc[mt][nt], a[mt], bf[nt]);
        }
        __syncthreads();   // all warps done reading As before staging over it

        // Stage fragments into As region as [96][OP] for coalesced stores
        float* Os = As;
        #pragma unroll
        for (int mt = 0; mt < 2; mt++)
            #pragma unroll
            for (int nt = 0; nt < 4; nt++) {
                int r = wm * 32 + mt * 16 + lr;
                int c = wn * 32 + nt * 8 + lc * 2;
                Os[r * OP + c]           = acc[mt][nt][0];
                Os[r * OP + c + 1]       = acc[mt][nt][1];
                Os[(r + 8) * OP + c]     = acc[mt][nt][2];
                Os[(r + 8) * OP + c + 1] = acc[mt][nt][3];
            }
        __syncthreads();

        // Coalesced write-out: 96 rows x 128 floats = 3072 float4s / 384 = 8 each
        #pragma unroll
        for (int i = 0; i < 8; i++) {
            int idx = tid + i * 384;
            int row = idx >> 5;
            int c4  = (idx & 31) << 2;
            float4 v = *reinterpret_cast<const float4*>(Os + row * OP + c4);
            *reinterpret_cast<float4*>(Yb + (size_t)(m0 + row) * P_ + n0 + c4) = v;
        }
    }
}

// ---------------------------------------------------------------------------
// Stage 3: multi-dilate window attention
// ---------------------------------------------------------------------------
__device__ __forceinline__ int reflect_i(int t, int n) {
    return t < 0 ? -t : (t >= n ? 2*n - 2 - t : t);
}

__global__ __launch_bounds__(256) void attn_kernel()
{
    int p    = blockIdx.x * 256 + threadIdx.x;
    int head = blockIdx.y & 1;
    int dil  = blockIdx.y >> 1;
    int b    = blockIdx.z;
    int dl   = dil + 1;

    int y  = p >> 7;
    int xx = p & 127;

    int nb[9];
    #pragma unroll
    for (int jy = 0; jy < 3; jy++) {
        int yy = reflect_i(y + (jy-1)*dl, H_);
        #pragma unroll
        for (int jx = 0; jx < 3; jx++) {
            int xc = reflect_i(xx + (jx-1)*dl, W_);
            nb[jy*3 + jx] = yy * W_ + xc;
        }
    }

    size_t chan0 = (size_t)b * MQKV + dil * C2 + head * HD;
    const float* qp = g_qkv + chan0 * P_;
    const float* kp = g_qkv + (chan0 + (size_t)C_)   * P_;
    const float* vp = g_qkv + (chan0 + (size_t)2*C_) * P_;

    float sc[9];
    #pragma unroll
    for (int j = 0; j < 9; j++) sc[j] = 0.f;

    #pragma unroll 4
    for (int d = 0; d < HD; d++) {
        float qd = qp[(size_t)d * P_ + p];
        const float* kr = kp + (size_t)d * P_;
        #pragma unroll
        for (int j = 0; j < 9; j++) sc[j] += qd * kr[nb[j]];
    }

    float mx = sc[0] * SCALE;
    #pragma unroll
    for (int j = 0; j < 9; j++) { sc[j] *= SCALE; mx = fmaxf(mx, sc[j]); }
    float sum = 0.f;
    #pragma unroll
    for (int j = 0; j < 9; j++) { sc[j] = __expf(sc[j] - mx); sum += sc[j]; }
    float inv = 1.f / sum;

    float* op = g_xo + ((size_t)b * C_ + dil * C2 + head * HD) * P_ + p;
    #pragma unroll 4
    for (int d = 0; d < HD; d++) {
        const float* vr = vp + (size_t)d * P_;
        float a = 0.f;
        #pragma unroll
        for (int j = 0; j < 9; j++) a += sc[j] * vr[nb[j]];
        op[(size_t)d * P_] = a * inv;
    }
}

// ---------------------------------------------------------------------------
extern "C" void kernel_launch(void* const* d_in, const int* in_sizes, int n_in,
                              void* d_out, int out_size)
{
    const float* x      = (const float*)d_in[0];
    const float* pos_w  = (const float*)d_in[1];
    const float* pos_b  = (const float*)d_in[2];
    const float* qkv_w  = (const float*)d_in[3];
    const float* proj_w = (const float*)d_in[4];
    float* out = (float*)d_out;

    float *gx, *gq, *go;
    cudaGetSymbolAddress((void**)&gx, g_x);
    cudaGetSymbolAddress((void**)&gq, g_qkv);
    cudaGetSymbolAddress((void**)&go, g_xo);

    cudaFuncSetAttribute(gemm_mma, cudaFuncAttributeMaxDynamicSharedMemorySize, SM_BYTES);

    // Stage 1: positional dwconv + residual + bias
    {
        int total = B_*C_*P_;
        pos_kernel<<<(total + 255)/256, 256>>>(x, pos_w, pos_b);
    }
    // Stage 2: qkv 1x1 conv (576 x 192 x 16384 per batch)
    {
        dim3 grid(P_/GBN, B_);
        gemm_mma<<<grid, 384, SM_BYTES>>>(qkv_w, gx, gq, MQKV);
    }
    // Stage 3: attention
    {
        dim3 grid(P_/256, NH*ND, B_);
        attn_kernel<<<grid, 256>>>();
    }
    // Stage 4: projection (192 x 192 x 16384 per batch)
    {
        dim3 grid(P_/GBN, B_);
        gemm_mma<<<grid, 384, SM_BYTES>>>(proj_w, go, out, C_);
    }
}